// round 8
// baseline (speedup 1.0000x reference)
#include <cuda_runtime.h>
#include <mma.h>
using namespace nvcuda;

#define BB 2
#define SS 2048
#define HH 768
#define NH 12
#define DD 64
#define BH (BB*NH)
#define M_PROJ (BB*SS)
#define OUT_ELEMS (BB*SS*HH)
#define ATTN_ELEMS ((size_t)BB*NH*SS*SS)

__device__ float g_qh[BB*NH*SS*DD];
__device__ float g_kh[BB*NH*SS*DD];
__device__ float g_vh[BB*NH*SS*DD];
__device__ float g_ctx[BB*SS*HH];
__device__ float g_linv[BH*SS];
__device__ float g_attn_scratch[BB*NH*SS*SS];

typedef wmma::fragment<wmma::matrix_a, 16, 16, 8, wmma::precision::tf32, wmma::row_major> FragA;
typedef wmma::fragment<wmma::matrix_b, 16, 16, 8, wmma::precision::tf32, wmma::col_major> FragBc;
typedef wmma::fragment<wmma::matrix_b, 16, 16, 8, wmma::precision::tf32, wmma::row_major> FragBr;
typedef wmma::fragment<wmma::accumulator, 16, 16, 8, float> FragC;

#define LDS 36           // 32-k slab + 4 pad (proj kernel)
#define SLABK 32
#define NSLAB (HH/SLABK) // 24
#define LDP 68           // 64 + 4
#define LDQ 132          // 128 + 4
#define LDT 20           // 16-k slab + 4 pad (out_proj kernel)

// scores are multiplied by 0.125 then exp'ed; in log2 domain:
// p = 2^(s * 0.125*log2(e) + b2),  b2 = 0 (unmasked) or -100 (masked -> ~2^-100 = 0)
#define SC_L2E 0.18033688011112042f
#define MASK_B2 (-100.0f)

#define CVT4(t4) do { \
    t4.x = wmma::__float_to_tf32(t4.x); t4.y = wmma::__float_to_tf32(t4.y); \
    t4.z = wmma::__float_to_tf32(t4.z); t4.w = wmma::__float_to_tf32(t4.w); } while(0)

// MUFU path: single-instruction exp2
__device__ __forceinline__ float exp2_mufu(float y) {
    float r;
    asm("ex2.approx.f32 %0, %1;" : "=f"(r) : "f"(y));
    return r;
}

// FMA-pipe path: magic-number range reduction + deg-4 poly + exponent add.
// Valid for y in (-126, 126); rel err ~5e-5.
__device__ __forceinline__ float exp2_poly(float y) {
    float t  = y + 12582912.0f;       // round-to-nearest int in mantissa
    float nf = t - 12582912.0f;
    float f  = y - nf;                // f in [-0.5, 0.5]
    float p = 0.00961813f;
    p = fmaf(p, f, 0.05550411f);
    p = fmaf(p, f, 0.24022651f);
    p = fmaf(p, f, 0.69314718f);
    p = fmaf(p, f, 1.00000000f);
    // low 9 bits of bits(12582912.0f)=0x4B400000 are zero -> (bits(t)<<23) == n<<23
    int sb = (__float_as_int(t) << 23);
    return __int_as_float(__float_as_int(p) + sb);
}

// ============================================================
// Kernel 1: fused QKV projections (128x128 tile, 32-k slab).
// ============================================================
__global__ void __launch_bounds__(256, 2)
proj_qkv_kernel(const float* __restrict__ q,
                const float* __restrict__ k,
                const float* __restrict__ v,
                const float* __restrict__ Wq, const float* __restrict__ bq,
                const float* __restrict__ Wk, const float* __restrict__ bk,
                const float* __restrict__ Wv, const float* __restrict__ bv) {
    const float* X; const float* W; const float* bias; float* Y;
    if (blockIdx.z == 0)      { X = q; W = Wq; bias = bq; Y = g_qh; }
    else if (blockIdx.z == 1) { X = k; W = Wk; bias = bk; Y = g_kh; }
    else                      { X = v; W = Wv; bias = bv; Y = g_vh; }

    extern __shared__ float sm[];
    float* As = sm;
    float* Bs = sm + 128 * LDS;
    float* Cs = sm;
    __shared__ float bias_s[128];

    const int tid = threadIdx.x;
    const int w = tid >> 5;
    const int m0 = blockIdx.y * 128, n0 = blockIdx.x * 128;
    const int wm = (w & 1) * 64, wn = (w >> 1) * 32;
    if (tid < 128) bias_s[tid] = bias[n0 + tid];

    FragC acc[4][2];
    #pragma unroll
    for (int i = 0; i < 4; i++)
        #pragma unroll
        for (int j = 0; j < 2; j++) wmma::fill_fragment(acc[i][j], 0.0f);

    const int r = tid >> 1;
    const int c0 = (tid & 1) * 16;
    const float* xp = X + (size_t)(m0 + r) * HH + c0;
    const float* wp = W + (size_t)(n0 + r) * HH + c0;

    for (int s = 0; s < NSLAB; s++) {
        #pragma unroll
        for (int i = 0; i < 4; i++) {
            float4 t4 = *(const float4*)(xp + s * SLABK + i * 4);
            CVT4(t4); *(float4*)&As[r * LDS + c0 + i * 4] = t4;
            float4 u4 = *(const float4*)(wp + s * SLABK + i * 4);
            CVT4(u4); *(float4*)&Bs[r * LDS + c0 + i * 4] = u4;
        }
        __syncthreads();
        #pragma unroll
        for (int kk = 0; kk < 4; kk++) {
            FragA a[4]; FragBc b[2];
            #pragma unroll
            for (int i = 0; i < 4; i++) wmma::load_matrix_sync(a[i], &As[(wm + i * 16) * LDS + kk * 8], LDS);
            #pragma unroll
            for (int j = 0; j < 2; j++) wmma::load_matrix_sync(b[j], &Bs[(wn + j * 16) * LDS + kk * 8], LDS);
            #pragma unroll
            for (int i = 0; i < 4; i++)
                #pragma unroll
                for (int j = 0; j < 2; j++) wmma::mma_sync(acc[i][j], a[i], b[j], acc[i][j]);
        }
        __syncthreads();
    }

    #pragma unroll
    for (int i = 0; i < 4; i++)
        #pragma unroll
        for (int j = 0; j < 2; j++)
            wmma::store_matrix_sync(&Cs[(wm + i * 16) * LDQ + wn + j * 16], acc[i][j], LDQ, wmma::mem_row_major);
    __syncthreads();

    {
        const int rr = tid >> 1;
        const int cc = (tid & 1) * 64;
        const int h = (n0 + cc) >> 6;
        const int m = m0 + rr, b = m >> 11, s = m & 2047;
        float* dst = &Y[(((size_t)b * NH + h) * SS + s) * DD];
        #pragma unroll
        for (int t = 0; t < 16; t++) {
            float4 t4 = *(float4*)&Cs[rr * LDQ + cc + t * 4];
            t4.x += bias_s[cc + t * 4];     t4.y += bias_s[cc + t * 4 + 1];
            t4.z += bias_s[cc + t * 4 + 2]; t4.w += bias_s[cc + t * 4 + 3];
            *(float4*)&dst[t * 4] = t4;
        }
    }
}

// ============================================================
// Kernel 2: fused attention. No-max softmax in log2 domain,
// hybrid MUFU/FMA exp2, unnormalized attn write, 1/sum -> g_linv.
// ============================================================
__global__ void __launch_bounds__(256, 2)
fused_attn_kernel(const int* __restrict__ mask, float* __restrict__ attn) {
    extern __shared__ float sm[];
    float* Qs    = sm;                    // [128][LDP]
    float* Ks    = Qs + 128 * LDP;        // [64][LDP]
    float* Vs    = Ks + 64 * LDP;         // [64][LDP]
    float* ps    = Vs + 64 * LDP;         // [128][LDP]
    float* biasv = ps + 128 * LDP;        // [2048]

    const int tid = threadIdx.x;
    const int w = tid >> 5;
    const int bh = blockIdx.y;
    const int b = bh / NH, h = bh % NH;
    const int m0 = blockIdx.x * 128;
    const int wm = (w >> 1) * 32, wn = (w & 1) * 32;

    const float* qh_head = g_qh + (size_t)bh * SS * DD + (size_t)m0 * DD;
    const float* kh_head = g_kh + (size_t)bh * SS * DD;
    const float* vh_head = g_vh + (size_t)bh * SS * DD;

    #pragma unroll
    for (int jj = 0; jj < 2; jj++) {
        int e = tid + 256 * jj;
        int r = e >> 2, cc = (e & 3) * 16;
        #pragma unroll
        for (int i = 0; i < 4; i++) {
            float4 t4 = *(const float4*)&qh_head[(size_t)r * DD + cc + i * 4];
            CVT4(t4);
            *(float4*)&Qs[r * LDP + cc + i * 4] = t4;
        }
    }
    #pragma unroll
    for (int i = 0; i < 8; i++) {
        int c = tid + 256 * i;
        biasv[c] = mask[b * SS + c] ? MASK_B2 : 0.0f;
    }
    __syncthreads();

    const int erow = tid >> 1, ec0 = (tid & 1) * 32;
    float l_run = 0.0f;

    FragC accv[2][2];
    #pragma unroll
    for (int i = 0; i < 2; i++)
        #pragma unroll
        for (int j = 0; j < 2; j++) wmma::fill_fragment(accv[i][j], 0.0f);

    float* arow = attn + ((size_t)bh * SS + m0 + erow) * SS;

    for (int c0 = 0; c0 < SS; c0 += 64) {
        {
            int kr = tid >> 2, cc = (tid & 3) * 16;
            const float* ksrc = kh_head + (size_t)(c0 + kr) * DD + cc;
            const float* vsrc = vh_head + (size_t)(c0 + kr) * DD + cc;
            #pragma unroll
            for (int i = 0; i < 4; i++) {
                float4 t4 = *(const float4*)(ksrc + i * 4);
                CVT4(t4); *(float4*)&Ks[kr * LDP + cc + i * 4] = t4;
                float4 u4 = *(const float4*)(vsrc + i * 4);
                CVT4(u4); *(float4*)&Vs[kr * LDP + cc + i * 4] = u4;
            }
        }
        __syncthreads();

        {
            FragC sa[2][2];
            #pragma unroll
            for (int i = 0; i < 2; i++)
                #pragma unroll
                for (int j = 0; j < 2; j++) wmma::fill_fragment(sa[i][j], 0.0f);
            #pragma unroll
            for (int kk = 0; kk < 8; kk++) {
                FragA a0, a1; FragBc b0, b1;
                wmma::load_matrix_sync(a0, &Qs[(wm +  0) * LDP + kk * 8], LDP);
                wmma::load_matrix_sync(a1, &Qs[(wm + 16) * LDP + kk * 8], LDP);
                wmma::load_matrix_sync(b0, &Ks[(wn +  0) * LDP + kk * 8], LDP);
                wmma::load_matrix_sync(b1, &Ks[(wn + 16) * LDP + kk * 8], LDP);
                wmma::mma_sync(sa[0][0], a0, b0, sa[0][0]);
                wmma::mma_sync(sa[0][1], a0, b1, sa[0][1]);
                wmma::mma_sync(sa[1][0], a1, b0, sa[1][0]);
                wmma::mma_sync(sa[1][1], a1, b1, sa[1][1]);
            }
            #pragma unroll
            for (int i = 0; i < 2; i++)
                #pragma unroll
                for (int j = 0; j < 2; j++)
                    wmma::store_matrix_sync(&ps[(wm + i * 16) * LDP + wn + j * 16], sa[i][j], LDP, wmma::mem_row_major);
        }
        __syncthreads();

        // ---- p = 2^(s*SC_L2E + b2): hybrid MUFU (18/32) + FMA-poly (14/32) ----
        {
            float lsum = 0.0f;
            #pragma unroll
            for (int i = 0; i < 8; i++) {
                int c = ec0 + i * 4;
                float4 t4 = *(float4*)&ps[erow * LDP + c];
                float4 b4 = *(const float4*)&biasv[c0 + c];
                float yx = fmaf(t4.x, SC_L2E, b4.x);
                float yy = fmaf(t4.y, SC_L2E, b4.y);
                float yz = fmaf(t4.z, SC_L2E, b4.z);
                float yw = fmaf(t4.w, SC_L2E, b4.w);
                float4 p4;
                if (i < 4) {                 // full MUFU
                    p4.x = exp2_mufu(yx); p4.y = exp2_mufu(yy);
                    p4.z = exp2_mufu(yz); p4.w = exp2_mufu(yw);
                } else if (i == 4) {         // half/half
                    p4.x = exp2_mufu(yx); p4.y = exp2_mufu(yy);
                    p4.z = exp2_poly(yz); p4.w = exp2_poly(yw);
                } else {                     // full FMA-pipe
                    p4.x = exp2_poly(yx); p4.y = exp2_poly(yy);
                    p4.z = exp2_poly(yz); p4.w = exp2_poly(yw);
                }
                lsum += p4.x + p4.y + p4.z + p4.w;
                *(float4*)&arow[c0 + c] = p4;   // unnormalized attn
                CVT4(p4);
                *(float4*)&ps[erow * LDP + c] = p4;
            }
            l_run += lsum;
        }
        __syncthreads();

        #pragma unroll
        for (int kk = 0; kk < 8; kk++) {
            FragA a0, a1; FragBr b0, b1;
            wmma::load_matrix_sync(a0, &ps[(wm +  0) * LDP + kk * 8], LDP);
            wmma::load_matrix_sync(a1, &ps[(wm + 16) * LDP + kk * 8], LDP);
            wmma::load_matrix_sync(b0, &Vs[(kk * 8) * LDP + wn +  0], LDP);
            wmma::load_matrix_sync(b1, &Vs[(kk * 8) * LDP + wn + 16], LDP);
            wmma::mma_sync(accv[0][0], a0, b0, accv[0][0]);
            wmma::mma_sync(accv[0][1], a0, b1, accv[0][1]);
            wmma::mma_sync(accv[1][0], a1, b0, accv[1][0]);
            wmma::mma_sync(accv[1][1], a1, b1, accv[1][1]);
        }
        __syncthreads();
    }

    l_run += __shfl_xor_sync(0xFFFFFFFFu, l_run, 1);
    const float inv_l = 1.0f / l_run;
    if ((tid & 1) == 0) g_linv[bh * SS + m0 + erow] = inv_l;

    #pragma unroll
    for (int i = 0; i < 2; i++)
        #pragma unroll
        for (int j = 0; j < 2; j++)
            wmma::store_matrix_sync(&ps[(wm + i * 16) * LDP + wn + j * 16], accv[i][j], LDP, wmma::mem_row_major);
    __syncthreads();
    {
        float* dst = &g_ctx[((size_t)(b * SS + m0 + erow)) * HH + h * 64 + ec0];
        #pragma unroll
        for (int i = 0; i < 8; i++) {
            float4 t4 = *(float4*)&ps[erow * LDP + ec0 + i * 4];
            t4.x *= inv_l; t4.y *= inv_l; t4.z *= inv_l; t4.w *= inv_l;
            *(float4*)&dst[i * 4] = t4;
        }
    }
}

// ============================================================
// Kernel 3: attn rescale (block per row, coalesced streaming).
// ============================================================
__global__ void __launch_bounds__(256)
attn_scale_kernel(float* __restrict__ attn) {
    const int row = blockIdx.x;
    const float inv = g_linv[row];
    float* p = attn + (size_t)row * SS;
    const int t = threadIdx.x;
    #pragma unroll
    for (int i = 0; i < 2; i++) {
        int c = (t + i * 256) * 4;
        float4 v4 = *(float4*)&p[c];
        v4.x *= inv; v4.y *= inv; v4.z *= inv; v4.w *= inv;
        *(float4*)&p[c] = v4;
    }
}

// ============================================================
// Kernel 4: out = ctx @ Wm^T + bm (128x64 tile, 16-k slab).
// ============================================================
__global__ void __launch_bounds__(256)
out_proj_kernel(const float* __restrict__ Wm,
                const float* __restrict__ bm,
                float* __restrict__ out) {
    __shared__ float sbuf[128 * LDP];
    __shared__ float bias_s[64];
    float* As = sbuf;
    float* Bs = sbuf + 128 * LDT;
    float* Cs = sbuf;

    const int tid = threadIdx.x;
    const int w = tid >> 5;
    const int m0 = blockIdx.y * 128, n0 = blockIdx.x * 64;
    const int mw = (w >> 1) * 32, nw = (w & 1) * 32;
    if (tid < 64) bias_s[tid] = bm[n0 + tid];

    FragC acc[2][2];
    #pragma unroll
    for (int i = 0; i < 2; i++)
        #pragma unroll
        for (int j = 0; j < 2; j++) wmma::fill_fragment(acc[i][j], 0.0f);

    for (int k0 = 0; k0 < HH; k0 += 16) {
        #pragma unroll
        for (int jj = 0; jj < 2; jj++) {
            int e = tid + 256 * jj;
            int r = e >> 2, c4 = (e & 3) * 4;
            float4 t4 = *(const float4*)&g_ctx[(size_t)(m0 + r) * HH + k0 + c4];
            CVT4(t4);
            *(float4*)&As[r * LDT + c4] = t4;
        }
        {
            int r = tid >> 2, c4 = (tid & 3) * 4;
            float4 t4 = *(const float4*)&Wm[(size_t)(n0 + r) * HH + k0 + c4];
            CVT4(t4);
            *(float4*)&Bs[r * LDT + c4] = t4;
        }
        __syncthreads();
        #pragma unroll
        for (int kt = 0; kt < 2; kt++) {
            FragA a0, a1; FragBc b0, b1;
            wmma::load_matrix_sync(a0, &As[(mw +  0) * LDT + kt * 8], LDT);
            wmma::load_matrix_sync(a1, &As[(mw + 16) * LDT + kt * 8], LDT);
            wmma::load_matrix_sync(b0, &Bs[(nw +  0) * LDT + kt * 8], LDT);
            wmma::load_matrix_sync(b1, &Bs[(nw + 16) * LDT + kt * 8], LDT);
            wmma::mma_sync(acc[0][0], a0, b0, acc[0][0]);
            wmma::mma_sync(acc[0][1], a0, b1, acc[0][1]);
            wmma::mma_sync(acc[1][0], a1, b0, acc[1][0]);
            wmma::mma_sync(acc[1][1], a1, b1, acc[1][1]);
        }
        __syncthreads();
    }
    #pragma unroll
    for (int i = 0; i < 2; i++)
        #pragma unroll
        for (int j = 0; j < 2; j++)
            wmma::store_matrix_sync(&Cs[(mw + i * 16) * LDP + nw + j * 16], acc[i][j], LDP, wmma::mem_row_major);
    __syncthreads();

    #pragma unroll
    for (int jj = 0; jj < 8; jj++) {
        int e = tid + 256 * jj;
        int r = e >> 4, c4 = (e & 15) * 4;
        float4 t4 = *(float4*)&Cs[r * LDP + c4];
        t4.x += bias_s[c4]; t4.y += bias_s[c4 + 1];
        t4.z += bias_s[c4 + 2]; t4.w += bias_s[c4 + 3];
        *(float4*)&out[(size_t)(m0 + r) * HH + n0 + c4] = t4;
    }
}

// ============================================================
// Host launcher
// ============================================================
extern "C" void kernel_launch(void* const* d_in, const int* in_sizes, int n_in,
                              void* d_out, int out_size) {
    const float* v    = (const float*)d_in[0];
    const float* k    = (const float*)d_in[1];
    const float* q    = (const float*)d_in[2];
    const int*   mask = (const int*)  d_in[3];
    const float* Wv   = (const float*)d_in[4];
    const float* bv   = (const float*)d_in[5];
    const float* Wk   = (const float*)d_in[6];
    const float* bk   = (const float*)d_in[7];
    const float* Wq   = (const float*)d_in[8];
    const float* bq   = (const float*)d_in[9];
    const float* Wm   = (const float*)d_in[10];
    const float* bm   = (const float*)d_in[11];
    float* out = (float*)d_out;

    float* attn;
    if ((size_t)out_size >= (size_t)OUT_ELEMS + ATTN_ELEMS) {
        attn = out + OUT_ELEMS;
    } else {
        void* p = nullptr;
        cudaGetSymbolAddress(&p, g_attn_scratch);
        attn = (float*)p;
    }

    const int SMEM_GEMM = 128 * LDQ * 4;                                            // 67584
    const int SMEM_FA   = (128 * LDP + 64 * LDP + 64 * LDP + 128 * LDP + 2048) * 4; // 112640
    static int smem_set = 0;
    if (!smem_set) {
        cudaFuncSetAttribute(proj_qkv_kernel, cudaFuncAttributeMaxDynamicSharedMemorySize, SMEM_GEMM);
        cudaFuncSetAttribute(fused_attn_kernel, cudaFuncAttributeMaxDynamicSharedMemorySize, SMEM_FA);
        smem_set = 1;
    }

    proj_qkv_kernel<<<dim3(HH / 128, M_PROJ / 128, 3), 256, SMEM_GEMM>>>(q, k, v, Wq, bq, Wk, bk, Wv, bv);
    fused_attn_kernel<<<dim3(SS / 128, BH), 256, SMEM_FA>>>(mask, attn);
    attn_scale_kernel<<<BH * SS, 256>>>(attn);
    out_proj_kernel<<<dim3(HH / 64, M_PROJ / 128, 1), 256>>>(Wm, bm, out);
}

// round 9
// speedup vs baseline: 1.0036x; 1.0036x over previous
#include <cuda_runtime.h>
#include <mma.h>
using namespace nvcuda;

#define BB 2
#define SS 2048
#define HH 768
#define NH 12
#define DD 64
#define BH (BB*NH)
#define M_PROJ (BB*SS)
#define OUT_ELEMS (BB*SS*HH)
#define ATTN_ELEMS ((size_t)BB*NH*SS*SS)

__device__ float g_qh[BB*NH*SS*DD];
__device__ float g_kh[BB*NH*SS*DD];
__device__ float g_vh[BB*NH*SS*DD];
__device__ float g_ctx[BB*SS*HH];
__device__ float g_cpart[2][BB*SS*HH];   // unnormalized partial AV per K-half
__device__ float g_lpart[2][BH*SS];      // partial exp-sums per K-half
__device__ float g_attn_scratch[BB*NH*SS*SS];

typedef wmma::fragment<wmma::matrix_a, 16, 16, 8, wmma::precision::tf32, wmma::row_major> FragA;
typedef wmma::fragment<wmma::matrix_b, 16, 16, 8, wmma::precision::tf32, wmma::col_major> FragBc;
typedef wmma::fragment<wmma::matrix_b, 16, 16, 8, wmma::precision::tf32, wmma::row_major> FragBr;
typedef wmma::fragment<wmma::accumulator, 16, 16, 8, float> FragC;

#define LDS 36           // 32-k slab + 4 pad (proj kernel)
#define SLABK 32
#define NSLAB (HH/SLABK) // 24
#define LDP 68           // 64 + 4
#define LDQ 132          // 128 + 4
#define LDT 20           // 16-k slab + 4 pad (out_proj kernel)
#define KHALF 1024       // K columns per attention CTA

// log2-domain softmax: p = 2^(s * 0.125*log2(e) + b2); masked b2 = -100
#define SC_L2E 0.18033688011112042f
#define MASK_B2 (-100.0f)

#define CVT4(t4) do { \
    t4.x = wmma::__float_to_tf32(t4.x); t4.y = wmma::__float_to_tf32(t4.y); \
    t4.z = wmma::__float_to_tf32(t4.z); t4.w = wmma::__float_to_tf32(t4.w); } while(0)

__device__ __forceinline__ float exp2_mufu(float y) {
    float r;
    asm("ex2.approx.f32 %0, %1;" : "=f"(r) : "f"(y));
    return r;
}

// ============================================================
// Kernel 1: fused QKV projections (128x128 tile, 32-k slab).
// ============================================================
__global__ void __launch_bounds__(256, 2)
proj_qkv_kernel(const float* __restrict__ q,
                const float* __restrict__ k,
                const float* __restrict__ v,
                const float* __restrict__ Wq, const float* __restrict__ bq,
                const float* __restrict__ Wk, const float* __restrict__ bk,
                const float* __restrict__ Wv, const float* __restrict__ bv) {
    const float* X; const float* W; const float* bias; float* Y;
    if (blockIdx.z == 0)      { X = q; W = Wq; bias = bq; Y = g_qh; }
    else if (blockIdx.z == 1) { X = k; W = Wk; bias = bk; Y = g_kh; }
    else                      { X = v; W = Wv; bias = bv; Y = g_vh; }

    extern __shared__ float sm[];
    float* As = sm;
    float* Bs = sm + 128 * LDS;
    float* Cs = sm;
    __shared__ float bias_s[128];

    const int tid = threadIdx.x;
    const int w = tid >> 5;
    const int m0 = blockIdx.y * 128, n0 = blockIdx.x * 128;
    const int wm = (w & 1) * 64, wn = (w >> 1) * 32;
    if (tid < 128) bias_s[tid] = bias[n0 + tid];

    FragC acc[4][2];
    #pragma unroll
    for (int i = 0; i < 4; i++)
        #pragma unroll
        for (int j = 0; j < 2; j++) wmma::fill_fragment(acc[i][j], 0.0f);

    const int r = tid >> 1;
    const int c0 = (tid & 1) * 16;
    const float* xp = X + (size_t)(m0 + r) * HH + c0;
    const float* wp = W + (size_t)(n0 + r) * HH + c0;

    for (int s = 0; s < NSLAB; s++) {
        #pragma unroll
        for (int i = 0; i < 4; i++) {
            float4 t4 = *(const float4*)(xp + s * SLABK + i * 4);
            CVT4(t4); *(float4*)&As[r * LDS + c0 + i * 4] = t4;
            float4 u4 = *(const float4*)(wp + s * SLABK + i * 4);
            CVT4(u4); *(float4*)&Bs[r * LDS + c0 + i * 4] = u4;
        }
        __syncthreads();
        #pragma unroll
        for (int kk = 0; kk < 4; kk++) {
            FragA a[4]; FragBc b[2];
            #pragma unroll
            for (int i = 0; i < 4; i++) wmma::load_matrix_sync(a[i], &As[(wm + i * 16) * LDS + kk * 8], LDS);
            #pragma unroll
            for (int j = 0; j < 2; j++) wmma::load_matrix_sync(b[j], &Bs[(wn + j * 16) * LDS + kk * 8], LDS);
            #pragma unroll
            for (int i = 0; i < 4; i++)
                #pragma unroll
                for (int j = 0; j < 2; j++) wmma::mma_sync(acc[i][j], a[i], b[j], acc[i][j]);
        }
        __syncthreads();
    }

    #pragma unroll
    for (int i = 0; i < 4; i++)
        #pragma unroll
        for (int j = 0; j < 2; j++)
            wmma::store_matrix_sync(&Cs[(wm + i * 16) * LDQ + wn + j * 16], acc[i][j], LDQ, wmma::mem_row_major);
    __syncthreads();

    {
        const int rr = tid >> 1;
        const int cc = (tid & 1) * 64;
        const int h = (n0 + cc) >> 6;
        const int m = m0 + rr, b = m >> 11, s = m & 2047;
        float* dst = &Y[(((size_t)b * NH + h) * SS + s) * DD];
        #pragma unroll
        for (int t = 0; t < 16; t++) {
            float4 t4 = *(float4*)&Cs[rr * LDQ + cc + t * 4];
            t4.x += bias_s[cc + t * 4];     t4.y += bias_s[cc + t * 4 + 1];
            t4.z += bias_s[cc + t * 4 + 2]; t4.w += bias_s[cc + t * 4 + 3];
            *(float4*)&dst[t * 4] = t4;
        }
    }
}

// ============================================================
// Kernel 2: fused attention, K-split 2-way.
// CTA = (128 Q rows) x (1024 K cols) of one (b,h).
// Writes unnormalized attn directly + partial AV/l to g_cpart/g_lpart.
// ============================================================
__global__ void __launch_bounds__(256, 2)
fused_attn_kernel(const int* __restrict__ mask, float* __restrict__ attn) {
    extern __shared__ float sm[];
    float* Qs    = sm;                    // [128][LDP]
    float* Ks    = Qs + 128 * LDP;        // [64][LDP]
    float* Vs    = Ks + 64 * LDP;         // [64][LDP]
    float* ps    = Vs + 64 * LDP;         // [128][LDP]
    float* biasv = ps + 128 * LDP;        // [KHALF]

    const int tid = threadIdx.x;
    const int w = tid >> 5;
    const int bh = blockIdx.y;
    const int b = bh / NH, h = bh % NH;
    const int m0 = blockIdx.x * 128;
    const int half = blockIdx.z;
    const int kbase = half * KHALF;
    const int wm = (w >> 1) * 32, wn = (w & 1) * 32;

    const float* qh_head = g_qh + (size_t)bh * SS * DD + (size_t)m0 * DD;
    const float* kh_head = g_kh + (size_t)bh * SS * DD;
    const float* vh_head = g_vh + (size_t)bh * SS * DD;

    #pragma unroll
    for (int jj = 0; jj < 2; jj++) {
        int e = tid + 256 * jj;
        int r = e >> 2, cc = (e & 3) * 16;
        #pragma unroll
        for (int i = 0; i < 4; i++) {
            float4 t4 = *(const float4*)&qh_head[(size_t)r * DD + cc + i * 4];
            CVT4(t4);
            *(float4*)&Qs[r * LDP + cc + i * 4] = t4;
        }
    }
    #pragma unroll
    for (int i = 0; i < 4; i++) {
        int c = tid + 256 * i;
        biasv[c] = mask[b * SS + kbase + c] ? MASK_B2 : 0.0f;
    }
    __syncthreads();

    const int erow = tid >> 1, ec0 = (tid & 1) * 32;
    float l_run = 0.0f;

    FragC accv[2][2];
    #pragma unroll
    for (int i = 0; i < 2; i++)
        #pragma unroll
        for (int j = 0; j < 2; j++) wmma::fill_fragment(accv[i][j], 0.0f);

    float* arow = attn + ((size_t)bh * SS + m0 + erow) * SS + kbase;

    for (int cl = 0; cl < KHALF; cl += 64) {
        const int c0 = kbase + cl;
        {
            int kr = tid >> 2, cc = (tid & 3) * 16;
            const float* ksrc = kh_head + (size_t)(c0 + kr) * DD + cc;
            const float* vsrc = vh_head + (size_t)(c0 + kr) * DD + cc;
            #pragma unroll
            for (int i = 0; i < 4; i++) {
                float4 t4 = *(const float4*)(ksrc + i * 4);
                CVT4(t4); *(float4*)&Ks[kr * LDP + cc + i * 4] = t4;
                float4 u4 = *(const float4*)(vsrc + i * 4);
                CVT4(u4); *(float4*)&Vs[kr * LDP + cc + i * 4] = u4;
            }
        }
        __syncthreads();

        {
            FragC sa[2][2];
            #pragma unroll
            for (int i = 0; i < 2; i++)
                #pragma unroll
                for (int j = 0; j < 2; j++) wmma::fill_fragment(sa[i][j], 0.0f);
            #pragma unroll
            for (int kk = 0; kk < 8; kk++) {
                FragA a0, a1; FragBc b0, b1;
                wmma::load_matrix_sync(a0, &Qs[(wm +  0) * LDP + kk * 8], LDP);
                wmma::load_matrix_sync(a1, &Qs[(wm + 16) * LDP + kk * 8], LDP);
                wmma::load_matrix_sync(b0, &Ks[(wn +  0) * LDP + kk * 8], LDP);
                wmma::load_matrix_sync(b1, &Ks[(wn + 16) * LDP + kk * 8], LDP);
                wmma::mma_sync(sa[0][0], a0, b0, sa[0][0]);
                wmma::mma_sync(sa[0][1], a0, b1, sa[0][1]);
                wmma::mma_sync(sa[1][0], a1, b0, sa[1][0]);
                wmma::mma_sync(sa[1][1], a1, b1, sa[1][1]);
            }
            #pragma unroll
            for (int i = 0; i < 2; i++)
                #pragma unroll
                for (int j = 0; j < 2; j++)
                    wmma::store_matrix_sync(&ps[(wm + i * 16) * LDP + wn + j * 16], sa[i][j], LDP, wmma::mem_row_major);
        }
        __syncthreads();

        {
            float lsum = 0.0f;
            #pragma unroll
            for (int i = 0; i < 8; i++) {
                int c = ec0 + i * 4;
                float4 t4 = *(float4*)&ps[erow * LDP + c];
                float4 b4 = *(const float4*)&biasv[cl + c];
                float4 p4;
                p4.x = exp2_mufu(fmaf(t4.x, SC_L2E, b4.x));
                p4.y = exp2_mufu(fmaf(t4.y, SC_L2E, b4.y));
                p4.z = exp2_mufu(fmaf(t4.z, SC_L2E, b4.z));
                p4.w = exp2_mufu(fmaf(t4.w, SC_L2E, b4.w));
                lsum += p4.x + p4.y + p4.z + p4.w;
                *(float4*)&arow[cl + c] = p4;   // unnormalized attn
                CVT4(p4);
                *(float4*)&ps[erow * LDP + c] = p4;
            }
            l_run += lsum;
        }
        __syncthreads();

        #pragma unroll
        for (int kk = 0; kk < 8; kk++) {
            FragA a0, a1; FragBr b0, b1;
            wmma::load_matrix_sync(a0, &ps[(wm +  0) * LDP + kk * 8], LDP);
            wmma::load_matrix_sync(a1, &ps[(wm + 16) * LDP + kk * 8], LDP);
            wmma::load_matrix_sync(b0, &Vs[(kk * 8) * LDP + wn +  0], LDP);
            wmma::load_matrix_sync(b1, &Vs[(kk * 8) * LDP + wn + 16], LDP);
            wmma::mma_sync(accv[0][0], a0, b0, accv[0][0]);
            wmma::mma_sync(accv[0][1], a0, b1, accv[0][1]);
            wmma::mma_sync(accv[1][0], a1, b0, accv[1][0]);
            wmma::mma_sync(accv[1][1], a1, b1, accv[1][1]);
        }
        __syncthreads();
    }

    l_run += __shfl_xor_sync(0xFFFFFFFFu, l_run, 1);
    if ((tid & 1) == 0) g_lpart[half][bh * SS + m0 + erow] = l_run;

    #pragma unroll
    for (int i = 0; i < 2; i++)
        #pragma unroll
        for (int j = 0; j < 2; j++)
            wmma::store_matrix_sync(&ps[(wm + i * 16) * LDP + wn + j * 16], accv[i][j], LDP, wmma::mem_row_major);
    __syncthreads();
    {
        float* dst = &g_cpart[half][((size_t)(b * SS + m0 + erow)) * HH + h * 64 + ec0];
        #pragma unroll
        for (int i = 0; i < 8; i++) {
            float4 t4 = *(float4*)&ps[erow * LDP + ec0 + i * 4];
            *(float4*)&dst[i * 4] = t4;   // unnormalized partial
        }
    }
}

// ============================================================
// Kernel 3: combine partial AV halves: ctx = (P0+P1)/(l0+l1).
// One block per (b,s) row; 192 threads x float4 = 768 cols.
// ============================================================
__global__ void __launch_bounds__(192)
combine_ctx_kernel() {
    const int row = blockIdx.x;           // b*SS + s
    const int b = row >> 11, s = row & 2047;
    __shared__ float inv_s[NH];
    if (threadIdx.x < NH) {
        int li = (b * NH + threadIdx.x) * SS + s;
        inv_s[threadIdx.x] = 1.0f / (g_lpart[0][li] + g_lpart[1][li]);
    }
    __syncthreads();
    const int n = threadIdx.x * 4;
    const float inv = inv_s[n >> 6];
    const size_t base = (size_t)row * HH + n;
    float4 a = *(const float4*)&g_cpart[0][base];
    float4 c = *(const float4*)&g_cpart[1][base];
    a.x = (a.x + c.x) * inv; a.y = (a.y + c.y) * inv;
    a.z = (a.z + c.z) * inv; a.w = (a.w + c.w) * inv;
    *(float4*)&g_ctx[base] = a;
}

// ============================================================
// Kernel 4: attn rescale (block per row, coalesced streaming).
// ============================================================
__global__ void __launch_bounds__(256)
attn_scale_kernel(float* __restrict__ attn) {
    const int row = blockIdx.x;
    const float inv = 1.0f / (g_lpart[0][row] + g_lpart[1][row]);
    float* p = attn + (size_t)row * SS;
    const int t = threadIdx.x;
    #pragma unroll
    for (int i = 0; i < 2; i++) {
        int c = (t + i * 256) * 4;
        float4 v4 = *(float4*)&p[c];
        v4.x *= inv; v4.y *= inv; v4.z *= inv; v4.w *= inv;
        *(float4*)&p[c] = v4;
    }
}

// ============================================================
// Kernel 5: out = ctx @ Wm^T + bm (128x64 tile, 16-k slab).
// ============================================================
__global__ void __launch_bounds__(256)
out_proj_kernel(const float* __restrict__ Wm,
                const float* __restrict__ bm,
                float* __restrict__ out) {
    __shared__ float sbuf[128 * LDP];
    __shared__ float bias_s[64];
    float* As = sbuf;
    float* Bs = sbuf + 128 * LDT;
    float* Cs = sbuf;

    const int tid = threadIdx.x;
    const int w = tid >> 5;
    const int m0 = blockIdx.y * 128, n0 = blockIdx.x * 64;
    const int mw = (w >> 1) * 32, nw = (w & 1) * 32;
    if (tid < 64) bias_s[tid] = bm[n0 + tid];

    FragC acc[2][2];
    #pragma unroll
    for (int i = 0; i < 2; i++)
        #pragma unroll
        for (int j = 0; j < 2; j++) wmma::fill_fragment(acc[i][j], 0.0f);

    for (int k0 = 0; k0 < HH; k0 += 16) {
        #pragma unroll
        for (int jj = 0; jj < 2; jj++) {
            int e = tid + 256 * jj;
            int r = e >> 2, c4 = (e & 3) * 4;
            float4 t4 = *(const float4*)&g_ctx[(size_t)(m0 + r) * HH + k0 + c4];
            CVT4(t4);
            *(float4*)&As[r * LDT + c4] = t4;
        }
        {
            int r = tid >> 2, c4 = (tid & 3) * 4;
            float4 t4 = *(const float4*)&Wm[(size_t)(n0 + r) * HH + k0 + c4];
            CVT4(t4);
            *(float4*)&Bs[r * LDT + c4] = t4;
        }
        __syncthreads();
        #pragma unroll
        for (int kt = 0; kt < 2; kt++) {
            FragA a0, a1; FragBc b0, b1;
            wmma::load_matrix_sync(a0, &As[(mw +  0) * LDT + kt * 8], LDT);
            wmma::load_matrix_sync(a1, &As[(mw + 16) * LDT + kt * 8], LDT);
            wmma::load_matrix_sync(b0, &Bs[(nw +  0) * LDT + kt * 8], LDT);
            wmma::load_matrix_sync(b1, &Bs[(nw + 16) * LDT + kt * 8], LDT);
            wmma::mma_sync(acc[0][0], a0, b0, acc[0][0]);
            wmma::mma_sync(acc[0][1], a0, b1, acc[0][1]);
            wmma::mma_sync(acc[1][0], a1, b0, acc[1][0]);
            wmma::mma_sync(acc[1][1], a1, b1, acc[1][1]);
        }
        __syncthreads();
    }
    #pragma unroll
    for (int i = 0; i < 2; i++)
        #pragma unroll
        for (int j = 0; j < 2; j++)
            wmma::store_matrix_sync(&Cs[(mw + i * 16) * LDP + nw + j * 16], acc[i][j], LDP, wmma::mem_row_major);
    __syncthreads();

    #pragma unroll
    for (int jj = 0; jj < 8; jj++) {
        int e = tid + 256 * jj;
        int r = e >> 4, c4 = (e & 15) * 4;
        float4 t4 = *(float4*)&Cs[r * LDP + c4];
        t4.x += bias_s[c4]; t4.y += bias_s[c4 + 1];
        t4.z += bias_s[c4 + 2]; t4.w += bias_s[c4 + 3];
        *(float4*)&out[(size_t)(m0 + r) * HH + n0 + c4] = t4;
    }
}

// ============================================================
// Host launcher
// ============================================================
extern "C" void kernel_launch(void* const* d_in, const int* in_sizes, int n_in,
                              void* d_out, int out_size) {
    const float* v    = (const float*)d_in[0];
    const float* k    = (const float*)d_in[1];
    const float* q    = (const float*)d_in[2];
    const int*   mask = (const int*)  d_in[3];
    const float* Wv   = (const float*)d_in[4];
    const float* bv   = (const float*)d_in[5];
    const float* Wk   = (const float*)d_in[6];
    const float* bk   = (const float*)d_in[7];
    const float* Wq   = (const float*)d_in[8];
    const float* bq   = (const float*)d_in[9];
    const float* Wm   = (const float*)d_in[10];
    const float* bm   = (const float*)d_in[11];
    float* out = (float*)d_out;

    float* attn;
    if ((size_t)out_size >= (size_t)OUT_ELEMS + ATTN_ELEMS) {
        attn = out + OUT_ELEMS;
    } else {
        void* p = nullptr;
        cudaGetSymbolAddress(&p, g_attn_scratch);
        attn = (float*)p;
    }

    const int SMEM_GEMM = 128 * LDQ * 4;                                             // 67584
    const int SMEM_FA   = (128 * LDP + 64 * LDP + 64 * LDP + 128 * LDP + KHALF) * 4; // 108544
    static int smem_set = 0;
    if (!smem_set) {
        cudaFuncSetAttribute(proj_qkv_kernel, cudaFuncAttributeMaxDynamicSharedMemorySize, SMEM_GEMM);
        cudaFuncSetAttribute(fused_attn_kernel, cudaFuncAttributeMaxDynamicSharedMemorySize, SMEM_FA);
        smem_set = 1;
    }

    proj_qkv_kernel<<<dim3(HH / 128, M_PROJ / 128, 3), 256, SMEM_GEMM>>>(q, k, v, Wq, bq, Wk, bk, Wv, bv);
    fused_attn_kernel<<<dim3(SS / 128, BH, 2), 256, SMEM_FA>>>(mask, attn);
    combine_ctx_kernel<<<BB * SS, 192>>>();
    attn_scale_kernel<<<BH * SS, 256>>>(attn);
    out_proj_kernel<<<dim3(HH / 64, M_PROJ / 128, 1), 256>>>(Wm, bm, out);
}

// round 10
// speedup vs baseline: 1.0788x; 1.0749x over previous
#include <cuda_runtime.h>
#include <mma.h>
using namespace nvcuda;

#define BB 2
#define SS 2048
#define HH 768
#define NH 12
#define DD 64
#define BH (BB*NH)
#define M_PROJ (BB*SS)
#define OUT_ELEMS (BB*SS*HH)
#define ATTN_ELEMS ((size_t)BB*NH*SS*SS)

__device__ float g_qh[BB*NH*SS*DD];
__device__ float g_kh[BB*NH*SS*DD];
__device__ float g_vh[BB*NH*SS*DD];
__device__ float g_ctx[BB*SS*HH];
__device__ float g_cpart[2][BB*SS*HH];   // unnormalized partial AV per K-half
__device__ float g_lpart[2][BH*SS];      // partial exp-sums per K-half
__device__ float g_attn_scratch[BB*NH*SS*SS];

typedef wmma::fragment<wmma::matrix_a, 16, 16, 8, wmma::precision::tf32, wmma::row_major> FragA;
typedef wmma::fragment<wmma::matrix_b, 16, 16, 8, wmma::precision::tf32, wmma::col_major> FragBc;
typedef wmma::fragment<wmma::matrix_b, 16, 16, 8, wmma::precision::tf32, wmma::row_major> FragBr;
typedef wmma::fragment<wmma::accumulator, 16, 16, 8, float> FragC;

#define LDS 36           // 32-k slab + 4 pad (proj kernel)
#define SLABK 32
#define NSLAB (HH/SLABK) // 24
#define LDP 68           // 64 + 4
#define LDQ 132          // 128 + 4
#define LDT 20           // 16-k slab + 4 pad (out_proj kernel)
#define KHALF 1024       // K columns per attention CTA

// log2-domain softmax: p = 2^(s * 0.125*log2(e) + b2); masked b2 = -100
#define SC_L2E 0.18033688011112042f
#define MASK_B2 (-100.0f)

#define CVT4(t4) do { \
    t4.x = wmma::__float_to_tf32(t4.x); t4.y = wmma::__float_to_tf32(t4.y); \
    t4.z = wmma::__float_to_tf32(t4.z); t4.w = wmma::__float_to_tf32(t4.w); } while(0)

__device__ __forceinline__ float exp2_mufu(float y) {
    float r;
    asm("ex2.approx.f32 %0, %1;" : "=f"(r) : "f"(y));
    return r;
}

// ============================================================
// Kernel 1: fused QKV projections (128x128 tile, 32-k slab).
// ============================================================
__global__ void __launch_bounds__(256, 2)
proj_qkv_kernel(const float* __restrict__ q,
                const float* __restrict__ k,
                const float* __restrict__ v,
                const float* __restrict__ Wq, const float* __restrict__ bq,
                const float* __restrict__ Wk, const float* __restrict__ bk,
                const float* __restrict__ Wv, const float* __restrict__ bv) {
    const float* X; const float* W; const float* bias; float* Y;
    if (blockIdx.z == 0)      { X = q; W = Wq; bias = bq; Y = g_qh; }
    else if (blockIdx.z == 1) { X = k; W = Wk; bias = bk; Y = g_kh; }
    else                      { X = v; W = Wv; bias = bv; Y = g_vh; }

    extern __shared__ float sm[];
    float* As = sm;
    float* Bs = sm + 128 * LDS;
    float* Cs = sm;
    __shared__ float bias_s[128];

    const int tid = threadIdx.x;
    const int w = tid >> 5;
    const int m0 = blockIdx.y * 128, n0 = blockIdx.x * 128;
    const int wm = (w & 1) * 64, wn = (w >> 1) * 32;
    if (tid < 128) bias_s[tid] = bias[n0 + tid];

    FragC acc[4][2];
    #pragma unroll
    for (int i = 0; i < 4; i++)
        #pragma unroll
        for (int j = 0; j < 2; j++) wmma::fill_fragment(acc[i][j], 0.0f);

    const int r = tid >> 1;
    const int c0 = (tid & 1) * 16;
    const float* xp = X + (size_t)(m0 + r) * HH + c0;
    const float* wp = W + (size_t)(n0 + r) * HH + c0;

    for (int s = 0; s < NSLAB; s++) {
        #pragma unroll
        for (int i = 0; i < 4; i++) {
            float4 t4 = *(const float4*)(xp + s * SLABK + i * 4);
            CVT4(t4); *(float4*)&As[r * LDS + c0 + i * 4] = t4;
            float4 u4 = *(const float4*)(wp + s * SLABK + i * 4);
            CVT4(u4); *(float4*)&Bs[r * LDS + c0 + i * 4] = u4;
        }
        __syncthreads();
        #pragma unroll
        for (int kk = 0; kk < 4; kk++) {
            FragA a[4]; FragBc b[2];
            #pragma unroll
            for (int i = 0; i < 4; i++) wmma::load_matrix_sync(a[i], &As[(wm + i * 16) * LDS + kk * 8], LDS);
            #pragma unroll
            for (int j = 0; j < 2; j++) wmma::load_matrix_sync(b[j], &Bs[(wn + j * 16) * LDS + kk * 8], LDS);
            #pragma unroll
            for (int i = 0; i < 4; i++)
                #pragma unroll
                for (int j = 0; j < 2; j++) wmma::mma_sync(acc[i][j], a[i], b[j], acc[i][j]);
        }
        __syncthreads();
    }

    #pragma unroll
    for (int i = 0; i < 4; i++)
        #pragma unroll
        for (int j = 0; j < 2; j++)
            wmma::store_matrix_sync(&Cs[(wm + i * 16) * LDQ + wn + j * 16], acc[i][j], LDQ, wmma::mem_row_major);
    __syncthreads();

    {
        const int rr = tid >> 1;
        const int cc = (tid & 1) * 64;
        const int h = (n0 + cc) >> 6;
        const int m = m0 + rr, b = m >> 11, s = m & 2047;
        float* dst = &Y[(((size_t)b * NH + h) * SS + s) * DD];
        #pragma unroll
        for (int t = 0; t < 16; t++) {
            float4 t4 = *(float4*)&Cs[rr * LDQ + cc + t * 4];
            t4.x += bias_s[cc + t * 4];     t4.y += bias_s[cc + t * 4 + 1];
            t4.z += bias_s[cc + t * 4 + 2]; t4.w += bias_s[cc + t * 4 + 3];
            *(float4*)&dst[t * 4] = t4;
        }
    }
}

// ============================================================
// Kernel 2: fused attention, K-split 2-way. Interleaved exp-phase
// column mapping for full 32B-sector gmem store coalescing.
// ============================================================
__global__ void __launch_bounds__(256, 2)
fused_attn_kernel(const int* __restrict__ mask, float* __restrict__ attn) {
    extern __shared__ float sm[];
    float* Qs    = sm;                    // [128][LDP]
    float* Ks    = Qs + 128 * LDP;        // [64][LDP]
    float* Vs    = Ks + 64 * LDP;         // [64][LDP]
    float* ps    = Vs + 64 * LDP;         // [128][LDP]
    float* biasv = ps + 128 * LDP;        // [KHALF]

    const int tid = threadIdx.x;
    const int w = tid >> 5;
    const int bh = blockIdx.y;
    const int b = bh / NH, h = bh % NH;
    const int m0 = blockIdx.x * 128;
    const int half = blockIdx.z;
    const int kbase = half * KHALF;
    const int wm = (w >> 1) * 32, wn = (w & 1) * 32;

    const float* qh_head = g_qh + (size_t)bh * SS * DD + (size_t)m0 * DD;
    const float* kh_head = g_kh + (size_t)bh * SS * DD;
    const float* vh_head = g_vh + (size_t)bh * SS * DD;

    #pragma unroll
    for (int jj = 0; jj < 2; jj++) {
        int e = tid + 256 * jj;
        int r = e >> 2, cc = (e & 3) * 16;
        #pragma unroll
        for (int i = 0; i < 4; i++) {
            float4 t4 = *(const float4*)&qh_head[(size_t)r * DD + cc + i * 4];
            CVT4(t4);
            *(float4*)&Qs[r * LDP + cc + i * 4] = t4;
        }
    }
    #pragma unroll
    for (int i = 0; i < 4; i++) {
        int c = tid + 256 * i;
        biasv[c] = mask[b * SS + kbase + c] ? MASK_B2 : 0.0f;
    }
    __syncthreads();

    const int erow = tid >> 1;
    const int cb   = (tid & 1) * 4;   // interleaved: lane pairs cover 32B together
    float l_run = 0.0f;

    FragC accv[2][2];
    #pragma unroll
    for (int i = 0; i < 2; i++)
        #pragma unroll
        for (int j = 0; j < 2; j++) wmma::fill_fragment(accv[i][j], 0.0f);

    float* arow = attn + ((size_t)bh * SS + m0 + erow) * SS + kbase;

    for (int cl = 0; cl < KHALF; cl += 64) {
        const int c0 = kbase + cl;
        {
            int kr = tid >> 2, cc = (tid & 3) * 16;
            const float* ksrc = kh_head + (size_t)(c0 + kr) * DD + cc;
            const float* vsrc = vh_head + (size_t)(c0 + kr) * DD + cc;
            #pragma unroll
            for (int i = 0; i < 4; i++) {
                float4 t4 = *(const float4*)(ksrc + i * 4);
                CVT4(t4); *(float4*)&Ks[kr * LDP + cc + i * 4] = t4;
                float4 u4 = *(const float4*)(vsrc + i * 4);
                CVT4(u4); *(float4*)&Vs[kr * LDP + cc + i * 4] = u4;
            }
        }
        __syncthreads();

        {
            FragC sa[2][2];
            #pragma unroll
            for (int i = 0; i < 2; i++)
                #pragma unroll
                for (int j = 0; j < 2; j++) wmma::fill_fragment(sa[i][j], 0.0f);
            #pragma unroll
            for (int kk = 0; kk < 8; kk++) {
                FragA a0, a1; FragBc b0, b1;
                wmma::load_matrix_sync(a0, &Qs[(wm +  0) * LDP + kk * 8], LDP);
                wmma::load_matrix_sync(a1, &Qs[(wm + 16) * LDP + kk * 8], LDP);
                wmma::load_matrix_sync(b0, &Ks[(wn +  0) * LDP + kk * 8], LDP);
                wmma::load_matrix_sync(b1, &Ks[(wn + 16) * LDP + kk * 8], LDP);
                wmma::mma_sync(sa[0][0], a0, b0, sa[0][0]);
                wmma::mma_sync(sa[0][1], a0, b1, sa[0][1]);
                wmma::mma_sync(sa[1][0], a1, b0, sa[1][0]);
                wmma::mma_sync(sa[1][1], a1, b1, sa[1][1]);
            }
            #pragma unroll
            for (int i = 0; i < 2; i++)
                #pragma unroll
                for (int j = 0; j < 2; j++)
                    wmma::store_matrix_sync(&ps[(wm + i * 16) * LDP + wn + j * 16], sa[i][j], LDP, wmma::mem_row_major);
        }
        __syncthreads();

        {
            float lsum = 0.0f;
            #pragma unroll
            for (int i = 0; i < 8; i++) {
                int c = cb + i * 8;
                float4 t4 = *(float4*)&ps[erow * LDP + c];
                float4 b4 = *(const float4*)&biasv[cl + c];
                float4 p4;
                p4.x = exp2_mufu(fmaf(t4.x, SC_L2E, b4.x));
                p4.y = exp2_mufu(fmaf(t4.y, SC_L2E, b4.y));
                p4.z = exp2_mufu(fmaf(t4.z, SC_L2E, b4.z));
                p4.w = exp2_mufu(fmaf(t4.w, SC_L2E, b4.w));
                lsum += p4.x + p4.y + p4.z + p4.w;
                *(float4*)&arow[cl + c] = p4;   // unnormalized attn (coalesced pairs)
                CVT4(p4);
                *(float4*)&ps[erow * LDP + c] = p4;
            }
            l_run += lsum;
        }
        __syncthreads();

        #pragma unroll
        for (int kk = 0; kk < 8; kk++) {
            FragA a0, a1; FragBr b0, b1;
            wmma::load_matrix_sync(a0, &ps[(wm +  0) * LDP + kk * 8], LDP);
            wmma::load_matrix_sync(a1, &ps[(wm + 16) * LDP + kk * 8], LDP);
            wmma::load_matrix_sync(b0, &Vs[(kk * 8) * LDP + wn +  0], LDP);
            wmma::load_matrix_sync(b1, &Vs[(kk * 8) * LDP + wn + 16], LDP);
            wmma::mma_sync(accv[0][0], a0, b0, accv[0][0]);
            wmma::mma_sync(accv[0][1], a0, b1, accv[0][1]);
            wmma::mma_sync(accv[1][0], a1, b0, accv[1][0]);
            wmma::mma_sync(accv[1][1], a1, b1, accv[1][1]);
        }
        __syncthreads();
    }

    l_run += __shfl_xor_sync(0xFFFFFFFFu, l_run, 1);
    if ((tid & 1) == 0) g_lpart[half][bh * SS + m0 + erow] = l_run;

    #pragma unroll
    for (int i = 0; i < 2; i++)
        #pragma unroll
        for (int j = 0; j < 2; j++)
            wmma::store_matrix_sync(&ps[(wm + i * 16) * LDP + wn + j * 16], accv[i][j], LDP, wmma::mem_row_major);
    __syncthreads();
    {
        float* dst = &g_cpart[half][((size_t)(b * SS + m0 + erow)) * HH + h * 64];
        #pragma unroll
        for (int i = 0; i < 8; i++) {
            int c = cb + i * 8;
            float4 t4 = *(float4*)&ps[erow * LDP + c];
            *(float4*)&dst[c] = t4;   // unnormalized partial, coalesced pairs
        }
    }
}

// ============================================================
// Kernel 3: combine partial AV halves: ctx = (P0+P1)/(l0+l1).
// ============================================================
__global__ void __launch_bounds__(192)
combine_ctx_kernel() {
    const int row = blockIdx.x;           // b*SS + s
    const int b = row >> 11, s = row & 2047;
    __shared__ float inv_s[NH];
    if (threadIdx.x < NH) {
        int li = (b * NH + threadIdx.x) * SS + s;
        inv_s[threadIdx.x] = 1.0f / (g_lpart[0][li] + g_lpart[1][li]);
    }
    __syncthreads();
    const int n = threadIdx.x * 4;
    const float inv = inv_s[n >> 6];
    const size_t base = (size_t)row * HH + n;
    float4 a = *(const float4*)&g_cpart[0][base];
    float4 c = *(const float4*)&g_cpart[1][base];
    a.x = (a.x + c.x) * inv; a.y = (a.y + c.y) * inv;
    a.z = (a.z + c.z) * inv; a.w = (a.w + c.w) * inv;
    *(float4*)&g_ctx[base] = a;
}

// ============================================================
// Kernel 4: attn rescale (block per row, coalesced streaming).
// ============================================================
__global__ void __launch_bounds__(256)
attn_scale_kernel(float* __restrict__ attn) {
    const int row = blockIdx.x;
    const float inv = 1.0f / (g_lpart[0][row] + g_lpart[1][row]);
    float* p = attn + (size_t)row * SS;
    const int t = threadIdx.x;
    #pragma unroll
    for (int i = 0; i < 2; i++) {
        int c = (t + i * 256) * 4;
        float4 v4 = *(float4*)&p[c];
        v4.x *= inv; v4.y *= inv; v4.z *= inv; v4.w *= inv;
        *(float4*)&p[c] = v4;
    }
}

// ============================================================
// Kernel 5: out = ctx @ Wm^T + bm (128x64 tile, 16-k slab).
// ============================================================
__global__ void __launch_bounds__(256)
out_proj_kernel(const float* __restrict__ Wm,
                const float* __restrict__ bm,
                float* __restrict__ out) {
    __shared__ float sbuf[128 * LDP];
    __shared__ float bias_s[64];
    float* As = sbuf;
    float* Bs = sbuf + 128 * LDT;
    float* Cs = sbuf;

    const int tid = threadIdx.x;
    const int w = tid >> 5;
    const int m0 = blockIdx.y * 128, n0 = blockIdx.x * 64;
    const int mw = (w >> 1) * 32, nw = (w & 1) * 32;
    if (tid < 64) bias_s[tid] = bm[n0 + tid];

    FragC acc[2][2];
    #pragma unroll
    for (int i = 0; i < 2; i++)
        #pragma unroll
        for (int j = 0; j < 2; j++) wmma::fill_fragment(acc[i][j], 0.0f);

    for (int k0 = 0; k0 < HH; k0 += 16) {
        #pragma unroll
        for (int jj = 0; jj < 2; jj++) {
            int e = tid + 256 * jj;
            int r = e >> 2, c4 = (e & 3) * 4;
            float4 t4 = *(const float4*)&g_ctx[(size_t)(m0 + r) * HH + k0 + c4];
            CVT4(t4);
            *(float4*)&As[r * LDT + c4] = t4;
        }
        {
            int r = tid >> 2, c4 = (tid & 3) * 4;
            float4 t4 = *(const float4*)&Wm[(size_t)(n0 + r) * HH + k0 + c4];
            CVT4(t4);
            *(float4*)&Bs[r * LDT + c4] = t4;
        }
        __syncthreads();
        #pragma unroll
        for (int kt = 0; kt < 2; kt++) {
            FragA a0, a1; FragBc b0, b1;
            wmma::load_matrix_sync(a0, &As[(mw +  0) * LDT + kt * 8], LDT);
            wmma::load_matrix_sync(a1, &As[(mw + 16) * LDT + kt * 8], LDT);
            wmma::load_matrix_sync(b0, &Bs[(nw +  0) * LDT + kt * 8], LDT);
            wmma::load_matrix_sync(b1, &Bs[(nw + 16) * LDT + kt * 8], LDT);
            wmma::mma_sync(acc[0][0], a0, b0, acc[0][0]);
            wmma::mma_sync(acc[0][1], a0, b1, acc[0][1]);
            wmma::mma_sync(acc[1][0], a1, b0, acc[1][0]);
            wmma::mma_sync(acc[1][1], a1, b1, acc[1][1]);
        }
        __syncthreads();
    }
    #pragma unroll
    for (int i = 0; i < 2; i++)
        #pragma unroll
        for (int j = 0; j < 2; j++)
            wmma::store_matrix_sync(&Cs[(mw + i * 16) * LDP + nw + j * 16], acc[i][j], LDP, wmma::mem_row_major);
    __syncthreads();

    #pragma unroll
    for (int jj = 0; jj < 8; jj++) {
        int e = tid + 256 * jj;
        int r = e >> 4, c4 = (e & 15) * 4;
        float4 t4 = *(float4*)&Cs[r * LDP + c4];
        t4.x += bias_s[c4]; t4.y += bias_s[c4 + 1];
        t4.z += bias_s[c4 + 2]; t4.w += bias_s[c4 + 3];
        *(float4*)&out[(size_t)(m0 + r) * HH + n0 + c4] = t4;
    }
}

// ============================================================
// Host launcher — attn_scale overlapped with combine+out_proj
// on a second stream (fork/join via events, graph-capturable).
// ============================================================
extern "C" void kernel_launch(void* const* d_in, const int* in_sizes, int n_in,
                              void* d_out, int out_size) {
    const float* v    = (const float*)d_in[0];
    const float* k    = (const float*)d_in[1];
    const float* q    = (const float*)d_in[2];
    const int*   mask = (const int*)  d_in[3];
    const float* Wv   = (const float*)d_in[4];
    const float* bv   = (const float*)d_in[5];
    const float* Wk   = (const float*)d_in[6];
    const float* bk   = (const float*)d_in[7];
    const float* Wq   = (const float*)d_in[8];
    const float* bq   = (const float*)d_in[9];
    const float* Wm   = (const float*)d_in[10];
    const float* bm   = (const float*)d_in[11];
    float* out = (float*)d_out;

    float* attn;
    if ((size_t)out_size >= (size_t)OUT_ELEMS + ATTN_ELEMS) {
        attn = out + OUT_ELEMS;
    } else {
        void* p = nullptr;
        cudaGetSymbolAddress(&p, g_attn_scratch);
        attn = (float*)p;
    }

    const int SMEM_GEMM = 128 * LDQ * 4;                                             // 67584
    const int SMEM_FA   = (128 * LDP + 64 * LDP + 64 * LDP + 128 * LDP + KHALF) * 4; // 108544
    static int init_done = 0;
    static cudaStream_t s2;
    static cudaEvent_t ev_fork, ev_join;
    if (!init_done) {
        cudaFuncSetAttribute(proj_qkv_kernel, cudaFuncAttributeMaxDynamicSharedMemorySize, SMEM_GEMM);
        cudaFuncSetAttribute(fused_attn_kernel, cudaFuncAttributeMaxDynamicSharedMemorySize, SMEM_FA);
        cudaStreamCreateWithFlags(&s2, cudaStreamNonBlocking);
        cudaEventCreateWithFlags(&ev_fork, cudaEventDisableTiming);
        cudaEventCreateWithFlags(&ev_join, cudaEventDisableTiming);
        init_done = 1;
    }

    proj_qkv_kernel<<<dim3(HH / 128, M_PROJ / 128, 3), 256, SMEM_GEMM>>>(q, k, v, Wq, bq, Wk, bk, Wv, bv);
    fused_attn_kernel<<<dim3(SS / 128, BH, 2), 256, SMEM_FA>>>(mask, attn);

    // fork: attn_scale on s2, concurrent with combine+out_proj on default
    cudaEventRecord(ev_fork, 0);
    cudaStreamWaitEvent(s2, ev_fork, 0);
    attn_scale_kernel<<<BH * SS, 256, 0, s2>>>(attn);
    cudaEventRecord(ev_join, s2);

    combine_ctx_kernel<<<BB * SS, 192>>>();
    out_proj_kernel<<<dim3(HH / 64, M_PROJ / 128, 1), 256>>>(Wm, bm, out);

    // join: default stream waits for attn_scale before returning
    cudaStreamWaitEvent(0, ev_join, 0);
}